// round 15
// baseline (speedup 1.0000x reference)
#include <cuda_runtime.h>
#include <cuda_bf16.h>
#include <cuda_fp16.h>
#include <math.h>
#include <stdint.h>

// ---------------- problem constants ----------------
#define BB    64
#define P0    729
#define CC    1152
#define HH    3584
#define HEADS 16
#define HD    72
#define TT    128
#define MROWS (BB*TT)     // 8192

// ---------------- scratch (device globals) ----------------
__device__ float g_xa[BB*P0*CC];
__device__ float g_xb[BB*P0*CC];
__device__ float g_sa[BB*P0];
__device__ float g_sb[BB*P0];
__device__ float g_metric[BB*P0*HD];
__device__ float g_nodemax[BB*384];
__device__ int   g_nodeidx[BB*384];
__device__ int   g_edgeidx[BB*384];
// fp16 operand buffers for tensor-core GEMMs
__device__ __align__(16) unsigned short g_a1[(long)MROWS*CC];     // A1 fp16
__device__ __align__(16) unsigned short g_a2[(long)MROWS*HH];     // A2 fp16 (gelu out)
__device__ __align__(16) unsigned short g_b1[(long)HH*CC];        // W1^T fp16
__device__ __align__(16) unsigned short g_b2[(long)HH*HH];        // W2^T fp16

__device__ __forceinline__ float* xbuf(int s){ return s ? g_xb : g_xa; }
__device__ __forceinline__ float* sbuf(int s){ return s ? g_sb : g_sa; }

// ---------------- portable PTX helpers (sm_80+) ----------------
__device__ __forceinline__ uint32_t smem_u32(const void* p){
    uint32_t a;
    asm("{ .reg .u64 t; cvta.to.shared.u64 t, %1; cvt.u32.u64 %0, t; }" : "=r"(a) : "l"(p));
    return a;
}
__device__ __forceinline__ void cp16(uint32_t dst, const void* src){
    asm volatile("cp.async.cg.shared.global [%0], [%1], 16;" :: "r"(dst), "l"(src) : "memory");
}
#define CP_COMMIT() asm volatile("cp.async.commit_group;" ::: "memory")
#define CP_WAIT(n)  asm volatile("cp.async.wait_group %0;" :: "n"(n) : "memory")

__device__ __forceinline__ void ldsm_x4(uint32_t& r0, uint32_t& r1, uint32_t& r2, uint32_t& r3, uint32_t addr){
    asm volatile("ldmatrix.sync.aligned.m8n8.x4.shared.b16 {%0,%1,%2,%3}, [%4];"
        : "=r"(r0), "=r"(r1), "=r"(r2), "=r"(r3) : "r"(addr));
}
__device__ __forceinline__ void mma16816h(float* d, const uint32_t* a, const uint32_t* b){
    asm volatile("mma.sync.aligned.m16n8k16.row.col.f32.f16.f16.f32 "
        "{%0,%1,%2,%3}, {%4,%5,%6,%7}, {%8,%9}, {%0,%1,%2,%3};"
        : "+f"(d[0]), "+f"(d[1]), "+f"(d[2]), "+f"(d[3])
        : "r"(a[0]), "r"(a[1]), "r"(a[2]), "r"(a[3]), "r"(b[0]), "r"(b[1]));
}

__device__ __forceinline__ unsigned short f16q(float a){
    __half h = __float2half_rn(a);
    return *(unsigned short*)&h;
}
// 3-way bf16 (decision scores; BF16x9 reference model — FROZEN)
__device__ __forceinline__ void bf16split3(float a, float& h, float& m, float& l){
    h = __bfloat162float(__float2bfloat16_rn(a));
    float r1 = __fadd_rn(a, -h);
    m = __bfloat162float(__float2bfloat16_rn(r1));
    float r2 = __fadd_rn(r1, -m);
    l = __bfloat162float(__float2bfloat16_rn(r2));
}

// ---------------- elementwise (vectorized) ----------------
__global__ void k_addpos(const float4* __restrict__ x, const float* __restrict__ pos){
    long i = (long)blockIdx.x * blockDim.x + threadIdx.x;
    const long n4 = (long)BB*P0*CC/4;
    if (i < n4){
        const long pc4 = (long)P0*CC/4;
        long pcv = i % pc4;
        float4 xv = x[i];
        const float4 pv = *(const float4*)(pos + pcv*4);
        float4 o;
        o.x = __fadd_rn(xv.x, pv.x);
        o.y = __fadd_rn(xv.y, pv.y);
        o.z = __fadd_rn(xv.z, pv.z);
        o.w = __fadd_rn(xv.w, pv.w);
        ((float4*)g_xa)[i] = o;
    }
}
__global__ void k_initsize(){
    int i = blockIdx.x*blockDim.x + threadIdx.x;
    if (i < BB*P0) g_sa[i] = 1.0f;
}

// ---------------- metric (frozen, passing) ----------------
__global__ void k_metric(int ssel, int t){
    int gw = blockIdx.x*4 + (threadIdx.x >> 5);
    if (gw >= BB*t) return;
    int lane = threadIdx.x & 31;
    const float* x = xbuf(ssel) + (long)gw*CC;
    float m0 = 0.f, m1 = 0.f, m2 = 0.f;
    #pragma unroll
    for (int h = 0; h < HEADS; h++){
        m0 = __fadd_rn(m0, x[h*HD + lane]);
        m1 = __fadd_rn(m1, x[h*HD + lane + 32]);
    }
    m0 = __fmul_rn(m0, 0.0625f);
    m1 = __fmul_rn(m1, 0.0625f);
    if (lane < 8){
        #pragma unroll
        for (int h = 0; h < HEADS; h++) m2 = __fadd_rn(m2, x[h*HD + lane + 64]);
        m2 = __fmul_rn(m2, 0.0625f);
    }
    float acc = __fmaf_rn(m0, m0, 0.0f);
    acc = __fmaf_rn(m1, m1, acc);
    if (lane < 8) acc = __fmaf_rn(m2, m2, acc);
    #pragma unroll
    for (int off = 16; off > 0; off >>= 1)
        acc = __fadd_rn(acc, __shfl_down_sync(0xffffffffu, acc, off));
    float nrm = __fsqrt_rn(__shfl_sync(0xffffffffu, acc, 0));
    float* Mo = g_metric + (long)gw*HD;
    Mo[lane]      = __fdiv_rn(m0, nrm);
    Mo[lane + 32] = __fdiv_rn(m1, nrm);
    if (lane < 8) Mo[lane + 64] = __fdiv_rn(m2, nrm);
}

// ---------------- scores: BF16x9-emulated dot (frozen, passing) ----------------
__global__ void k_scores(int t, int na, int nb){
    int bid = blockIdx.x;
    int b = bid / na, i = bid % na;
    const float* M = g_metric + (long)b*t*HD;
    __shared__ float ah[HD], am[HD], al[HD];
    int tid = threadIdx.x;
    if (tid < HD){
        float av = M[(long)(2*i)*HD + tid];
        float h, m, l; bf16split3(av, h, m, l);
        ah[tid] = h; am[tid] = m; al[tid] = l;
    }
    __syncthreads();
    float bv = -2.0f; int bi = 0x7fffffff;
    for (int j = tid; j < nb; j += blockDim.x){
        const float* br = M + (long)(2*j+1)*HD;
        float s_ll=0.f,s_lm=0.f,s_ml=0.f,s_lh=0.f,s_mm=0.f,s_hl=0.f,s_mh=0.f,s_hm=0.f,s_hh=0.f;
        #pragma unroll 8
        for (int k = 0; k < HD; k++){
            float bh, bm, bl; bf16split3(br[k], bh, bm, bl);
            float Ah = ah[k], Am = am[k], Al = al[k];
            s_ll = __fmaf_rn(Al, bl, s_ll);
            s_lm = __fmaf_rn(Al, bm, s_lm);
            s_ml = __fmaf_rn(Am, bl, s_ml);
            s_lh = __fmaf_rn(Al, bh, s_lh);
            s_mm = __fmaf_rn(Am, bm, s_mm);
            s_hl = __fmaf_rn(Ah, bl, s_hl);
            s_mh = __fmaf_rn(Am, bh, s_mh);
            s_hm = __fmaf_rn(Ah, bm, s_hm);
            s_hh = __fmaf_rn(Ah, bh, s_hh);
        }
        float acc = s_ll;
        acc = __fadd_rn(acc, s_lm);
        acc = __fadd_rn(acc, s_ml);
        acc = __fadd_rn(acc, s_lh);
        acc = __fadd_rn(acc, s_mm);
        acc = __fadd_rn(acc, s_hl);
        acc = __fadd_rn(acc, s_mh);
        acc = __fadd_rn(acc, s_hm);
        acc = __fadd_rn(acc, s_hh);
        if (acc > bv){ bv = acc; bi = j; }
    }
    __shared__ float sv[128]; __shared__ int si[128];
    sv[tid] = bv; si[tid] = bi;
    __syncthreads();
    for (int s = 64; s > 0; s >>= 1){
        if (tid < s){
            if (sv[tid+s] > sv[tid] || (sv[tid+s] == sv[tid] && si[tid+s] < si[tid])){
                sv[tid] = sv[tid+s]; si[tid] = si[tid+s];
            }
        }
        __syncthreads();
    }
    if (tid == 0){ g_nodemax[b*384+i] = sv[0]; g_nodeidx[b*384+i] = si[0]; }
}

// ---------------- sort / unm / dst (frozen, passing) ----------------
__global__ void k_sort(int n){
    int b = blockIdx.x, tid = threadIdx.x, npad = blockDim.x;
    extern __shared__ float smemf[];
    float* v  = smemf;
    int*   id = (int*)(smemf + npad);
    v[tid]  = (tid < n) ? g_nodemax[b*384+tid] : -3.4e38f;
    id[tid] = (tid < n) ? tid : 0x7fffffff;
    __syncthreads();
    for (int k = 2; k <= npad; k <<= 1){
        for (int j = k >> 1; j > 0; j >>= 1){
            int ixj = tid ^ j;
            if (ixj > tid){
                bool up = ((tid & k) == 0);
                bool before = (v[tid] > v[ixj]) || (v[tid] == v[ixj] && id[tid] < id[ixj]);
                if (up ? !before : before){
                    float tv = v[tid]; v[tid] = v[ixj]; v[ixj] = tv;
                    int   ti = id[tid]; id[tid] = id[ixj]; id[ixj] = ti;
                }
            }
            __syncthreads();
        }
    }
    if (tid < n) g_edgeidx[b*384+tid] = id[tid];
}

__global__ void k_unm(int ssel, int dsel, int t, int tn, int r, int unm){
    int bid = blockIdx.x;
    int b = bid / unm, u = bid % unm;
    int e = g_edgeidx[b*384 + r + u];
    const float* xs = xbuf(ssel) + ((long)b*t + 2*e)*CC;
    float*       xd = xbuf(dsel) + ((long)b*tn + u)*CC;
    float s = sbuf(ssel)[(long)b*t + 2*e];
    for (int d = threadIdx.x; d < CC; d += blockDim.x)
        xd[d] = __fdiv_rn(__fmul_rn(xs[d], s), s);
    if (threadIdx.x == 0) sbuf(dsel)[(long)b*tn + u] = s;
}

__global__ void k_dst(int ssel, int dsel, int t, int tn, int nb, int r, int unm){
    int bid = blockIdx.x;
    int b = bid / nb, j = bid % nb;
    __shared__ int   se[368];
    __shared__ int   sn[368];
    __shared__ int   match[368];
    __shared__ float msz[368];
    __shared__ int   nm;
    __shared__ float tsz, osz;
    const float* ss = sbuf(ssel) + (long)b*t;
    for (int k = threadIdx.x; k < r; k += blockDim.x){
        int s = g_edgeidx[b*384+k];
        se[k] = s;
        sn[k] = g_nodeidx[b*384+s];
    }
    __syncthreads();
    if (threadIdx.x == 0){
        int c = 0;
        float os = ss[2*j+1];
        float ts = os;
        for (int k = 0; k < r; k++){
            if (sn[k] == j){
                int s = se[k];
                float sz = ss[2*s];
                match[c] = s; msz[c] = sz;
                ts = __fadd_rn(ts, sz);
                c++;
            }
        }
        nm = c; tsz = ts; osz = os;
    }
    __syncthreads();
    const float* xs = xbuf(ssel) + (long)b*t*CC;
    float*       xd = xbuf(dsel) + ((long)b*tn + unm + j)*CC;
    int lnm = nm; float ltsz = tsz, losz = osz;
    for (int d = threadIdx.x; d < CC; d += blockDim.x){
        float acc = __fmul_rn(xs[(long)(2*j+1)*CC + d], losz);
        for (int m = 0; m < lnm; m++)
            acc = __fadd_rn(acc, __fmul_rn(xs[(long)(2*match[m])*CC + d], msz[m]));
        xd[d] = __fdiv_rn(acc, ltsz);
    }
    if (threadIdx.x == 0) sbuf(dsel)[(long)b*tn + unm + j] = ltsz;
}

// ---------------- prep: quantize merged x to fp16 (vectorized) ----------------
__global__ void k_splitx(){
    long i = (long)blockIdx.x * blockDim.x + threadIdx.x;
    const long n4 = (long)MROWS*CC/4;
    if (i < n4){
        float4 v = ((const float4*)g_xb)[i];
        ushort4 o;
        o.x = f16q(v.x); o.y = f16q(v.y); o.z = f16q(v.z); o.w = f16q(v.w);
        ((ushort4*)g_a1)[i] = o;
    }
}

// ---------------- prep: transpose+quantize weights W[K,N] -> B[N,K] fp16 ----------------
__global__ void k_splitw(const float* __restrict__ W,
                         unsigned short* __restrict__ Bq, int K, int N){
    __shared__ float tile[32][33];
    int kb = blockIdx.y*32, nb = blockIdx.x*32;
    int tx = threadIdx.x & 31, ty = threadIdx.x >> 5;
    for (int i = ty; i < 32; i += 8)
        tile[i][tx] = W[(long)(kb+i)*N + nb + tx];
    __syncthreads();
    for (int i = ty; i < 32; i += 8){
        long o = (long)(nb+i)*K + kb + tx;
        Bq[o] = f16q(tile[tx][i]);
    }
}

// ---------------- fp16 HMMA GEMM (portable mma.sync) ----------------
// C[M,N] = A[M,K] x B[N,K]^T ; single fp16 operands, f32 accum.
// CTA 128x128, K-chunk 64, 5-stage cp.async ring (prefetch 3 ahead);
// 8 warps 2(M)x4(N), warp tile 64x32 = 4x4 m16n8k16.
// SMEM rows padded to 72 halves (144B): bank idx (36r+4g) mod 32 conflict-free.
#define RS      72
#define TILE_B  (128*RS*2)      // 18432 bytes per operand array
#define BUF_B   (2*TILE_B)      // A, B
#define NSTAGE  5
#define GSMEM   (NSTAGE*BUF_B)  // 184320 bytes

template<int DO_GELU>
__global__ __launch_bounds__(256) void k_mmagemm(
    const unsigned short* __restrict__ A,
    const unsigned short* __restrict__ B,
    const float* __restrict__ bias, int K,
    float* __restrict__ Cf, unsigned short* __restrict__ C2)
{
    extern __shared__ char smemc[];
    uint32_t sb = smem_u32(smemc);
    int tid = threadIdx.x, lane = tid & 31, wid = tid >> 5;
    int wm = wid & 1, wn = wid >> 1;
    long m0 = (long)blockIdx.y*128, n0 = (long)blockIdx.x*128;
    int nc = K / 64;

    float acc[4][4][4];
    #pragma unroll
    for (int a = 0; a < 4; a++)
        #pragma unroll
        for (int b = 0; b < 4; b++)
            #pragma unroll
            for (int c = 0; c < 4; c++) acc[a][b][c] = 0.f;

    const unsigned short* srcs[2] = {A, B};
    long r0s[2]; r0s[0] = m0; r0s[1] = n0;

    auto load_buf = [&](int buf, int c){
        int k0 = c * 64;
        uint32_t base = sb + buf*BUF_B;
        #pragma unroll
        for (int a = 0; a < 2; a++){
            #pragma unroll
            for (int i = 0; i < 4; i++){
                int idx = tid + i*256;            // 0..1023
                int row = idx >> 3, g = idx & 7;  // 128 rows x 8 granules(8 halves)
                uint32_t dst = base + a*TILE_B + row*144 + g*16;
                cp16(dst, srcs[a] + (r0s[a]+row)*(long)K + k0 + g*8);
            }
        }
    };

    auto comp = [&](int buf){
        uint32_t base  = sb + buf*BUF_B;
        uint32_t baseA = base, baseB = base + TILE_B;
        #pragma unroll
        for (int ks = 0; ks < 4; ks++){
            // B frags: 2 x ldmatrix.x4, each covers two n-tiles (both k halves)
            uint32_t bfr[4][2];
            {
                int half = (lane >> 3) & 1;           // 0: k-half0, 1: k-half1
                int nsel = lane >> 4;                 // 0: first tile, 1: second
                int brow0 = wn*32 + (0 + nsel)*8 + (lane & 7);
                int brow1 = wn*32 + (2 + nsel)*8 + (lane & 7);
                int g = ks*2 + half;
                ldsm_x4(bfr[0][0], bfr[0][1], bfr[1][0], bfr[1][1], baseB + brow0*144 + g*16);
                ldsm_x4(bfr[2][0], bfr[2][1], bfr[3][0], bfr[3][1], baseB + brow1*144 + g*16);
            }
            #pragma unroll
            for (int mi = 0; mi < 4; mi++){
                int arow = wm*64 + mi*16 + (lane & 15);
                int ag = ks*2 + (lane >> 4);
                uint32_t a_f[4];
                ldsm_x4(a_f[0], a_f[1], a_f[2], a_f[3], baseA + arow*144 + ag*16);
                #pragma unroll
                for (int ni = 0; ni < 4; ni++)
                    mma16816h(acc[mi][ni], a_f, bfr[ni]);
            }
        }
    };

    load_buf(0, 0); CP_COMMIT();
    if (nc > 1){ load_buf(1, 1); CP_COMMIT(); }
    if (nc > 2){ load_buf(2, 2); CP_COMMIT(); }
    for (int c = 0; c < nc; c++){
        int younger = nc - 1 - c; if (younger > 2) younger = 2;
        if (younger >= 2)      { CP_WAIT(2); }
        else if (younger == 1) { CP_WAIT(1); }
        else                   { CP_WAIT(0); }
        __syncthreads();
        comp(c % NSTAGE);
        if (c + 3 < nc){ load_buf((c+3) % NSTAGE, c+3); CP_COMMIT(); }
    }

    // epilogue: m16n8k16 d mapping: row = l/4 + (r>=2)*8; col = (l%4)*2 + (r&1)
    #pragma unroll
    for (int mi = 0; mi < 4; mi++){
        #pragma unroll
        for (int ni = 0; ni < 4; ni++){
            #pragma unroll
            for (int r = 0; r < 4; r++){
                long m = m0 + wm*64 + mi*16 + (lane >> 2) + ((r >> 1) << 3);
                long n = n0 + wn*32 + ni*8  + ((lane & 3) << 1) + (r & 1);
                float v = __fadd_rn(acc[mi][ni][r], __ldg(bias + n));
                if (DO_GELU){
                    v = 0.5f*v*(1.0f + erff(v*0.70710678118654752f));
                    C2[m*HH + n] = f16q(v);
                } else {
                    Cf[m*HH + n] = v;
                }
            }
        }
    }
}

// ---------------- launcher ----------------
extern "C" void kernel_launch(void* const* d_in, const int* in_sizes, int n_in,
                              void* d_out, int out_size){
    const float* x   = (const float*)d_in[0];
    const float* pos = (const float*)d_in[1];
    const float* w1  = (const float*)d_in[2];
    const float* b1  = (const float*)d_in[3];
    const float* w2  = (const float*)d_in[4];
    const float* b2  = (const float*)d_in[5];
    float* out = (float*)d_out;

    void *p_a1, *p_a2, *p_b1, *p_b2;
    cudaGetSymbolAddress(&p_a1, g_a1); cudaGetSymbolAddress(&p_a2, g_a2);
    cudaGetSymbolAddress(&p_b1, g_b1); cudaGetSymbolAddress(&p_b2, g_b2);

    cudaFuncSetAttribute(k_mmagemm<1>, cudaFuncAttributeMaxDynamicSharedMemorySize, GSMEM);
    cudaFuncSetAttribute(k_mmagemm<0>, cudaFuncAttributeMaxDynamicSharedMemorySize, GSMEM);

    {
        long n4 = (long)BB*P0*CC/4;
        k_addpos<<<(unsigned)((n4 + 255)/256), 256>>>((const float4*)x, pos);
        k_initsize<<<(BB*P0 + 255)/256, 256>>>();
    }

    // weight prep (independent of merges)
    k_splitw<<<dim3(HH/32, CC/32), 256>>>(w1, (unsigned short*)p_b1, CC, HH);
    k_splitw<<<dim3(HH/32, HH/32), 256>>>(w2, (unsigned short*)p_b2, HH, HH);

    // merge schedule: 729 -> 365 -> 183 -> 128, r = {364, 182, 55}
    const int T[4] = {729, 365, 183, 128};
    const int R[3] = {364, 182, 55};
    int ssel = 0;
    for (int it = 0; it < 3; it++){
        int t = T[it], tn = T[it+1];
        int na = (t + 1) / 2, nb = t / 2;
        int r = R[it], unm = na - r;
        int dsel = 1 - ssel;
        int npad = 1; while (npad < na) npad <<= 1;

        k_metric<<<(BB*t + 3)/4, 128>>>(ssel, t);
        k_scores<<<BB*na, 128>>>(t, na, nb);
        k_sort<<<BB, npad, npad*8>>>(na);
        k_unm<<<BB*unm, 128>>>(ssel, dsel, t, tn, r, unm);
        k_dst<<<BB*nb, 128>>>(ssel, dsel, t, tn, nb, r, unm);
        ssel = dsel;
    }
    // merged tokens now in g_xb (64x128x1152)

    {
        long n4 = (long)MROWS*CC/4;
        k_splitx<<<(unsigned)((n4 + 255)/256), 256>>>();
    }

    dim3 gg(HH/128, MROWS/128);   // 28 x 64
    k_mmagemm<1><<<gg, 256, GSMEM>>>(
        (const unsigned short*)p_a1, (const unsigned short*)p_b1,
        b1, CC, nullptr, (unsigned short*)p_a2);
    k_mmagemm<0><<<gg, 256, GSMEM>>>(
        (const unsigned short*)p_a2, (const unsigned short*)p_b2,
        b2, HH, out, nullptr);
}

// round 16
// speedup vs baseline: 1.6241x; 1.6241x over previous
#include <cuda_runtime.h>
#include <cuda_bf16.h>
#include <cuda_fp16.h>
#include <math.h>
#include <stdint.h>

// ---------------- problem constants ----------------
#define BB    64
#define P0    729
#define CC    1152
#define HH    3584
#define HEADS 16
#define HD    72
#define TT    128
#define MROWS (BB*TT)     // 8192

// ---------------- scratch (device globals) ----------------
__device__ float g_xa[BB*P0*CC];
__device__ float g_xb[BB*P0*CC];
__device__ float g_sa[BB*P0];
__device__ float g_sb[BB*P0];
__device__ float g_metric[BB*P0*HD];
__device__ float g_nodemax[BB*384];
__device__ int   g_nodeidx[BB*384];
__device__ int   g_edgeidx[BB*384];
// fp16 operand buffers for tensor-core GEMMs
__device__ __align__(16) unsigned short g_a1[(long)MROWS*CC];     // A1 fp16
__device__ __align__(16) unsigned short g_a2[(long)MROWS*HH];     // A2 fp16 (gelu out)
__device__ __align__(16) unsigned short g_b1[(long)HH*CC];        // W1^T fp16
__device__ __align__(16) unsigned short g_b2[(long)HH*HH];        // W2^T fp16

__device__ __forceinline__ float* xbuf(int s){ return s ? g_xb : g_xa; }
__device__ __forceinline__ float* sbuf(int s){ return s ? g_sb : g_sa; }

// ---------------- portable PTX helpers (sm_80+) ----------------
__device__ __forceinline__ uint32_t smem_u32(const void* p){
    uint32_t a;
    asm("{ .reg .u64 t; cvta.to.shared.u64 t, %1; cvt.u32.u64 %0, t; }" : "=r"(a) : "l"(p));
    return a;
}
__device__ __forceinline__ void cp16(uint32_t dst, const void* src){
    asm volatile("cp.async.cg.shared.global [%0], [%1], 16;" :: "r"(dst), "l"(src) : "memory");
}
#define CP_COMMIT() asm volatile("cp.async.commit_group;" ::: "memory")
#define CP_WAIT(n)  asm volatile("cp.async.wait_group %0;" :: "n"(n) : "memory")

__device__ __forceinline__ void ldsm_x4(uint32_t& r0, uint32_t& r1, uint32_t& r2, uint32_t& r3, uint32_t addr){
    asm volatile("ldmatrix.sync.aligned.m8n8.x4.shared.b16 {%0,%1,%2,%3}, [%4];"
        : "=r"(r0), "=r"(r1), "=r"(r2), "=r"(r3) : "r"(addr));
}
__device__ __forceinline__ void mma16816h(float* d, const uint32_t* a, const uint32_t* b){
    asm volatile("mma.sync.aligned.m16n8k16.row.col.f32.f16.f16.f32 "
        "{%0,%1,%2,%3}, {%4,%5,%6,%7}, {%8,%9}, {%0,%1,%2,%3};"
        : "+f"(d[0]), "+f"(d[1]), "+f"(d[2]), "+f"(d[3])
        : "r"(a[0]), "r"(a[1]), "r"(a[2]), "r"(a[3]), "r"(b[0]), "r"(b[1]));
}

__device__ __forceinline__ unsigned short f16q(float a){
    __half h = __float2half_rn(a);
    return *(unsigned short*)&h;
}
// 3-way bf16 (decision scores; BF16x9 reference model — FROZEN)
__device__ __forceinline__ void bf16split3(float a, float& h, float& m, float& l){
    h = __bfloat162float(__float2bfloat16_rn(a));
    float r1 = __fadd_rn(a, -h);
    m = __bfloat162float(__float2bfloat16_rn(r1));
    float r2 = __fadd_rn(r1, -m);
    l = __bfloat162float(__float2bfloat16_rn(r2));
}

// ---------------- elementwise (vectorized) ----------------
__global__ void k_addpos(const float4* __restrict__ x, const float* __restrict__ pos){
    long i = (long)blockIdx.x * blockDim.x + threadIdx.x;
    const long n4 = (long)BB*P0*CC/4;
    if (i < n4){
        const long pc4 = (long)P0*CC/4;
        long pcv = i % pc4;
        float4 xv = x[i];
        const float4 pv = *(const float4*)(pos + pcv*4);
        float4 o;
        o.x = __fadd_rn(xv.x, pv.x);
        o.y = __fadd_rn(xv.y, pv.y);
        o.z = __fadd_rn(xv.z, pv.z);
        o.w = __fadd_rn(xv.w, pv.w);
        ((float4*)g_xa)[i] = o;
    }
}
__global__ void k_initsize(){
    int i = blockIdx.x*blockDim.x + threadIdx.x;
    if (i < BB*P0) g_sa[i] = 1.0f;
}

// ---------------- metric (frozen, passing) ----------------
__global__ void k_metric(int ssel, int t){
    int gw = blockIdx.x*4 + (threadIdx.x >> 5);
    if (gw >= BB*t) return;
    int lane = threadIdx.x & 31;
    const float* x = xbuf(ssel) + (long)gw*CC;
    float m0 = 0.f, m1 = 0.f, m2 = 0.f;
    #pragma unroll
    for (int h = 0; h < HEADS; h++){
        m0 = __fadd_rn(m0, x[h*HD + lane]);
        m1 = __fadd_rn(m1, x[h*HD + lane + 32]);
    }
    m0 = __fmul_rn(m0, 0.0625f);
    m1 = __fmul_rn(m1, 0.0625f);
    if (lane < 8){
        #pragma unroll
        for (int h = 0; h < HEADS; h++) m2 = __fadd_rn(m2, x[h*HD + lane + 64]);
        m2 = __fmul_rn(m2, 0.0625f);
    }
    float acc = __fmaf_rn(m0, m0, 0.0f);
    acc = __fmaf_rn(m1, m1, acc);
    if (lane < 8) acc = __fmaf_rn(m2, m2, acc);
    #pragma unroll
    for (int off = 16; off > 0; off >>= 1)
        acc = __fadd_rn(acc, __shfl_down_sync(0xffffffffu, acc, off));
    float nrm = __fsqrt_rn(__shfl_sync(0xffffffffu, acc, 0));
    float* Mo = g_metric + (long)gw*HD;
    Mo[lane]      = __fdiv_rn(m0, nrm);
    Mo[lane + 32] = __fdiv_rn(m1, nrm);
    if (lane < 8) Mo[lane + 64] = __fdiv_rn(m2, nrm);
}

// ---------------- scores: BF16x9-emulated dot (frozen, passing) ----------------
__global__ void k_scores(int t, int na, int nb){
    int bid = blockIdx.x;
    int b = bid / na, i = bid % na;
    const float* M = g_metric + (long)b*t*HD;
    __shared__ float ah[HD], am[HD], al[HD];
    int tid = threadIdx.x;
    if (tid < HD){
        float av = M[(long)(2*i)*HD + tid];
        float h, m, l; bf16split3(av, h, m, l);
        ah[tid] = h; am[tid] = m; al[tid] = l;
    }
    __syncthreads();
    float bv = -2.0f; int bi = 0x7fffffff;
    for (int j = tid; j < nb; j += blockDim.x){
        const float* br = M + (long)(2*j+1)*HD;
        float s_ll=0.f,s_lm=0.f,s_ml=0.f,s_lh=0.f,s_mm=0.f,s_hl=0.f,s_mh=0.f,s_hm=0.f,s_hh=0.f;
        #pragma unroll 8
        for (int k = 0; k < HD; k++){
            float bh, bm, bl; bf16split3(br[k], bh, bm, bl);
            float Ah = ah[k], Am = am[k], Al = al[k];
            s_ll = __fmaf_rn(Al, bl, s_ll);
            s_lm = __fmaf_rn(Al, bm, s_lm);
            s_ml = __fmaf_rn(Am, bl, s_ml);
            s_lh = __fmaf_rn(Al, bh, s_lh);
            s_mm = __fmaf_rn(Am, bm, s_mm);
            s_hl = __fmaf_rn(Ah, bl, s_hl);
            s_mh = __fmaf_rn(Am, bh, s_mh);
            s_hm = __fmaf_rn(Ah, bm, s_hm);
            s_hh = __fmaf_rn(Ah, bh, s_hh);
        }
        float acc = s_ll;
        acc = __fadd_rn(acc, s_lm);
        acc = __fadd_rn(acc, s_ml);
        acc = __fadd_rn(acc, s_lh);
        acc = __fadd_rn(acc, s_mm);
        acc = __fadd_rn(acc, s_hl);
        acc = __fadd_rn(acc, s_mh);
        acc = __fadd_rn(acc, s_hm);
        acc = __fadd_rn(acc, s_hh);
        if (acc > bv){ bv = acc; bi = j; }
    }
    __shared__ float sv[128]; __shared__ int si[128];
    sv[tid] = bv; si[tid] = bi;
    __syncthreads();
    for (int s = 64; s > 0; s >>= 1){
        if (tid < s){
            if (sv[tid+s] > sv[tid] || (sv[tid+s] == sv[tid] && si[tid+s] < si[tid])){
                sv[tid] = sv[tid+s]; si[tid] = si[tid+s];
            }
        }
        __syncthreads();
    }
    if (tid == 0){ g_nodemax[b*384+i] = sv[0]; g_nodeidx[b*384+i] = si[0]; }
}

// ---------------- sort / unm / dst (frozen, passing) ----------------
__global__ void k_sort(int n){
    int b = blockIdx.x, tid = threadIdx.x, npad = blockDim.x;
    extern __shared__ float smemf[];
    float* v  = smemf;
    int*   id = (int*)(smemf + npad);
    v[tid]  = (tid < n) ? g_nodemax[b*384+tid] : -3.4e38f;
    id[tid] = (tid < n) ? tid : 0x7fffffff;
    __syncthreads();
    for (int k = 2; k <= npad; k <<= 1){
        for (int j = k >> 1; j > 0; j >>= 1){
            int ixj = tid ^ j;
            if (ixj > tid){
                bool up = ((tid & k) == 0);
                bool before = (v[tid] > v[ixj]) || (v[tid] == v[ixj] && id[tid] < id[ixj]);
                if (up ? !before : before){
                    float tv = v[tid]; v[tid] = v[ixj]; v[ixj] = tv;
                    int   ti = id[tid]; id[tid] = id[ixj]; id[ixj] = ti;
                }
            }
            __syncthreads();
        }
    }
    if (tid < n) g_edgeidx[b*384+tid] = id[tid];
}

__global__ void k_unm(int ssel, int dsel, int t, int tn, int r, int unm){
    int bid = blockIdx.x;
    int b = bid / unm, u = bid % unm;
    int e = g_edgeidx[b*384 + r + u];
    const float* xs = xbuf(ssel) + ((long)b*t + 2*e)*CC;
    float*       xd = xbuf(dsel) + ((long)b*tn + u)*CC;
    float s = sbuf(ssel)[(long)b*t + 2*e];
    for (int d = threadIdx.x; d < CC; d += blockDim.x)
        xd[d] = __fdiv_rn(__fmul_rn(xs[d], s), s);
    if (threadIdx.x == 0) sbuf(dsel)[(long)b*tn + u] = s;
}

__global__ void k_dst(int ssel, int dsel, int t, int tn, int nb, int r, int unm){
    int bid = blockIdx.x;
    int b = bid / nb, j = bid % nb;
    __shared__ int   se[368];
    __shared__ int   sn[368];
    __shared__ int   match[368];
    __shared__ float msz[368];
    __shared__ int   nm;
    __shared__ float tsz, osz;
    const float* ss = sbuf(ssel) + (long)b*t;
    for (int k = threadIdx.x; k < r; k += blockDim.x){
        int s = g_edgeidx[b*384+k];
        se[k] = s;
        sn[k] = g_nodeidx[b*384+s];
    }
    __syncthreads();
    if (threadIdx.x == 0){
        int c = 0;
        float os = ss[2*j+1];
        float ts = os;
        for (int k = 0; k < r; k++){
            if (sn[k] == j){
                int s = se[k];
                float sz = ss[2*s];
                match[c] = s; msz[c] = sz;
                ts = __fadd_rn(ts, sz);
                c++;
            }
        }
        nm = c; tsz = ts; osz = os;
    }
    __syncthreads();
    const float* xs = xbuf(ssel) + (long)b*t*CC;
    float*       xd = xbuf(dsel) + ((long)b*tn + unm + j)*CC;
    int lnm = nm; float ltsz = tsz, losz = osz;
    for (int d = threadIdx.x; d < CC; d += blockDim.x){
        float acc = __fmul_rn(xs[(long)(2*j+1)*CC + d], losz);
        for (int m = 0; m < lnm; m++)
            acc = __fadd_rn(acc, __fmul_rn(xs[(long)(2*match[m])*CC + d], msz[m]));
        xd[d] = __fdiv_rn(acc, ltsz);
    }
    if (threadIdx.x == 0) sbuf(dsel)[(long)b*tn + unm + j] = ltsz;
}

// ---------------- prep: quantize merged x to fp16 (vectorized) ----------------
__global__ void k_splitx(){
    long i = (long)blockIdx.x * blockDim.x + threadIdx.x;
    const long n4 = (long)MROWS*CC/4;
    if (i < n4){
        float4 v = ((const float4*)g_xb)[i];
        ushort4 o;
        o.x = f16q(v.x); o.y = f16q(v.y); o.z = f16q(v.z); o.w = f16q(v.w);
        ((ushort4*)g_a1)[i] = o;
    }
}

// ---------------- prep: transpose+quantize weights W[K,N] -> B[N,K] fp16 ----------------
__global__ void k_splitw(const float* __restrict__ W,
                         unsigned short* __restrict__ Bq, int K, int N){
    __shared__ float tile[32][33];
    int kb = blockIdx.y*32, nb = blockIdx.x*32;
    int tx = threadIdx.x & 31, ty = threadIdx.x >> 5;
    for (int i = ty; i < 32; i += 8)
        tile[i][tx] = W[(long)(kb+i)*N + nb + tx];
    __syncthreads();
    for (int i = ty; i < 32; i += 8){
        long o = (long)(nb+i)*K + kb + tx;
        Bq[o] = f16q(tile[tx][i]);
    }
}

// ---------------- fp16 HMMA GEMM (portable mma.sync) ----------------
// R14 config (proven fastest): CTA 128x128, K-chunk 64, 3-stage cp.async ring,
// 2 CTAs/SM; 8 warps 2(M)x4(N), warp tile 64x32 = 4x4 m16n8k16.
// B fragments via ldmatrix.x4 (validated in R15, numerics identical).
// SMEM rows padded to 72 halves (144B): bank idx (36r+4g) mod 32 conflict-free.
#define RS      72
#define TILE_B  (128*RS*2)      // 18432 bytes per operand array
#define BUF_B   (2*TILE_B)      // A, B
#define NSTAGE  3
#define GSMEM   (NSTAGE*BUF_B)  // 110592 bytes

template<int DO_GELU>
__global__ __launch_bounds__(256, 2) void k_mmagemm(
    const unsigned short* __restrict__ A,
    const unsigned short* __restrict__ B,
    const float* __restrict__ bias, int K,
    float* __restrict__ Cf, unsigned short* __restrict__ C2)
{
    extern __shared__ char smemc[];
    uint32_t sb = smem_u32(smemc);
    int tid = threadIdx.x, lane = tid & 31, wid = tid >> 5;
    int wm = wid & 1, wn = wid >> 1;
    long m0 = (long)blockIdx.y*128, n0 = (long)blockIdx.x*128;
    int nc = K / 64;

    float acc[4][4][4];
    #pragma unroll
    for (int a = 0; a < 4; a++)
        #pragma unroll
        for (int b = 0; b < 4; b++)
            #pragma unroll
            for (int c = 0; c < 4; c++) acc[a][b][c] = 0.f;

    const unsigned short* srcs[2] = {A, B};
    long r0s[2]; r0s[0] = m0; r0s[1] = n0;

    auto load_buf = [&](int buf, int c){
        int k0 = c * 64;
        uint32_t base = sb + buf*BUF_B;
        #pragma unroll
        for (int a = 0; a < 2; a++){
            #pragma unroll
            for (int i = 0; i < 4; i++){
                int idx = tid + i*256;            // 0..1023
                int row = idx >> 3, g = idx & 7;  // 128 rows x 8 granules(8 halves)
                uint32_t dst = base + a*TILE_B + row*144 + g*16;
                cp16(dst, srcs[a] + (r0s[a]+row)*(long)K + k0 + g*8);
            }
        }
    };

    auto comp = [&](int buf){
        uint32_t base  = sb + buf*BUF_B;
        uint32_t baseA = base, baseB = base + TILE_B;
        #pragma unroll
        for (int ks = 0; ks < 4; ks++){
            // B frags: 2 x ldmatrix.x4, each covers two n-tiles (both k halves)
            uint32_t bfr[4][2];
            {
                int half = (lane >> 3) & 1;           // 0: k-half0, 1: k-half1
                int nsel = lane >> 4;                 // 0: first tile, 1: second
                int brow0 = wn*32 + (0 + nsel)*8 + (lane & 7);
                int brow1 = wn*32 + (2 + nsel)*8 + (lane & 7);
                int g = ks*2 + half;
                ldsm_x4(bfr[0][0], bfr[0][1], bfr[1][0], bfr[1][1], baseB + brow0*144 + g*16);
                ldsm_x4(bfr[2][0], bfr[2][1], bfr[3][0], bfr[3][1], baseB + brow1*144 + g*16);
            }
            #pragma unroll
            for (int mi = 0; mi < 4; mi++){
                int arow = wm*64 + mi*16 + (lane & 15);
                int ag = ks*2 + (lane >> 4);
                uint32_t a_f[4];
                ldsm_x4(a_f[0], a_f[1], a_f[2], a_f[3], baseA + arow*144 + ag*16);
                #pragma unroll
                for (int ni = 0; ni < 4; ni++)
                    mma16816h(acc[mi][ni], a_f, bfr[ni]);
            }
        }
    };

    load_buf(0, 0); CP_COMMIT();
    load_buf(1, 1); CP_COMMIT();
    for (int c = 0; c < nc; c++){
        if (c + 1 < nc){ CP_WAIT(1); } else { CP_WAIT(0); }
        __syncthreads();
        comp(c % NSTAGE);
        if (c + 2 < nc){ load_buf((c+2) % NSTAGE, c+2); CP_COMMIT(); }
    }

    // epilogue: m16n8k16 d mapping: row = l/4 + (r>=2)*8; col = (l%4)*2 + (r&1)
    #pragma unroll
    for (int mi = 0; mi < 4; mi++){
        #pragma unroll
        for (int ni = 0; ni < 4; ni++){
            #pragma unroll
            for (int r = 0; r < 4; r++){
                long m = m0 + wm*64 + mi*16 + (lane >> 2) + ((r >> 1) << 3);
                long n = n0 + wn*32 + ni*8  + ((lane & 3) << 1) + (r & 1);
                float v = __fadd_rn(acc[mi][ni][r], __ldg(bias + n));
                if (DO_GELU){
                    v = 0.5f*v*(1.0f + erff(v*0.70710678118654752f));
                    C2[m*HH + n] = f16q(v);
                } else {
                    Cf[m*HH + n] = v;
                }
            }
        }
    }
}

// ---------------- launcher ----------------
extern "C" void kernel_launch(void* const* d_in, const int* in_sizes, int n_in,
                              void* d_out, int out_size){
    const float* x   = (const float*)d_in[0];
    const float* pos = (const float*)d_in[1];
    const float* w1  = (const float*)d_in[2];
    const float* b1  = (const float*)d_in[3];
    const float* w2  = (const float*)d_in[4];
    const float* b2  = (const float*)d_in[5];
    float* out = (float*)d_out;

    void *p_a1, *p_a2, *p_b1, *p_b2;
    cudaGetSymbolAddress(&p_a1, g_a1); cudaGetSymbolAddress(&p_a2, g_a2);
    cudaGetSymbolAddress(&p_b1, g_b1); cudaGetSymbolAddress(&p_b2, g_b2);

    cudaFuncSetAttribute(k_mmagemm<1>, cudaFuncAttributeMaxDynamicSharedMemorySize, GSMEM);
    cudaFuncSetAttribute(k_mmagemm<0>, cudaFuncAttributeMaxDynamicSharedMemorySize, GSMEM);

    {
        long n4 = (long)BB*P0*CC/4;
        k_addpos<<<(unsigned)((n4 + 255)/256), 256>>>((const float4*)x, pos);
        k_initsize<<<(BB*P0 + 255)/256, 256>>>();
    }

    // weight prep (independent of merges)
    k_splitw<<<dim3(HH/32, CC/32), 256>>>(w1, (unsigned short*)p_b1, CC, HH);
    k_splitw<<<dim3(HH/32, HH/32), 256>>>(w2, (unsigned short*)p_b2, HH, HH);

    // merge schedule: 729 -> 365 -> 183 -> 128, r = {364, 182, 55}
    const int T[4] = {729, 365, 183, 128};
    const int R[3] = {364, 182, 55};
    int ssel = 0;
    for (int it = 0; it < 3; it++){
        int t = T[it], tn = T[it+1];
        int na = (t + 1) / 2, nb = t / 2;
        int r = R[it], unm = na - r;
        int dsel = 1 - ssel;
        int npad = 1; while (npad < na) npad <<= 1;

        k_metric<<<(BB*t + 3)/4, 128>>>(ssel, t);
        k_scores<<<BB*na, 128>>>(t, na, nb);
        k_sort<<<BB, npad, npad*8>>>(na);
        k_unm<<<BB*unm, 128>>>(ssel, dsel, t, tn, r, unm);
        k_dst<<<BB*nb, 128>>>(ssel, dsel, t, tn, nb, r, unm);
        ssel = dsel;
    }
    // merged tokens now in g_xb (64x128x1152)

    {
        long n4 = (long)MROWS*CC/4;
        k_splitx<<<(unsigned)((n4 + 255)/256), 256>>>();
    }

    dim3 gg(HH/128, MROWS/128);   // 28 x 64
    k_mmagemm<1><<<gg, 256, GSMEM>>>(
        (const unsigned short*)p_a1, (const unsigned short*)p_b1,
        b1, CC, nullptr, (unsigned short*)p_a2);
    k_mmagemm<0><<<gg, 256, GSMEM>>>(
        (const unsigned short*)p_a2, (const unsigned short*)p_b2,
        b2, HH, out, nullptr);
}